// round 7
// baseline (speedup 1.0000x reference)
#include <cuda_runtime.h>
#include <cfloat>
#include <cstdint>

#define NCOLS 1000
#define TPB   64
#define NWARP 2
#define ROWS_PER_CTA 8
#define NSTAGE 2
#define ROW_BYTES 4000        // NCOLS * 4, multiple of 16
#define BUF_FLOATS 1024       // row + pad

// Order-preserving float<->uint mapping
__device__ __forceinline__ unsigned ford(float f) {
    unsigned u = __float_as_uint(f);
    return ((int)u < 0) ? ~u : (u | 0x80000000u);
}
__device__ __forceinline__ float funord(unsigned u) {
    return __uint_as_float(((int)u < 0) ? (u ^ 0x80000000u) : ~u);
}

__device__ __forceinline__ uint32_t smem_u32(const void* p) {
    uint32_t a;
    asm("{ .reg .u64 t; cvta.to.shared.u64 t, %1; cvt.u32.u64 %0, t; }" : "=r"(a) : "l"(p));
    return a;
}

#define MBAR_WAIT_ACQ(addr, par) do {                                          \
    asm volatile(                                                              \
        "{\n\t.reg .pred P1;\n\t"                                              \
        "WAIT_LOOP_%=:\n\t"                                                    \
        "mbarrier.try_wait.parity.acquire.cta.shared::cta.b64 P1, [%0], %1, 0x989680;\n\t" \
        "@P1 bra.uni WAIT_DONE_%=;\n\t"                                        \
        "bra.uni WAIT_LOOP_%=;\n\t"                                            \
        "WAIT_DONE_%=:\n\t}"                                                   \
        :: "r"(addr), "r"(par) : "memory");                                    \
} while (0)

#define MBAR_WAIT_RLX(addr, par) do {                                          \
    asm volatile(                                                              \
        "{\n\t.reg .pred P1;\n\t"                                              \
        "WAIT_LOOP_%=:\n\t"                                                    \
        "mbarrier.try_wait.parity.relaxed.cta.shared::cta.b64 P1, [%0], %1, 0x989680;\n\t" \
        "@P1 bra.uni WAIT_DONE_%=;\n\t"                                        \
        "bra.uni WAIT_LOOP_%=;\n\t"                                            \
        "WAIT_DONE_%=:\n\t}"                                                   \
        :: "r"(addr), "r"(par) : "memory");                                    \
} while (0)

// Exact warp top-2 in ordered-uint domain (per-lane o1 >= o2 on entry).
__device__ __forceinline__ void warp_top2(unsigned& o1, unsigned& o2) {
    unsigned r1  = __reduce_max_sync(0xFFFFFFFFu, o1);
    unsigned bal = __ballot_sync(0xFFFFFFFFu, o1 == r1);
    unsigned u   = (o1 == r1) ? o2 : o1;
    unsigned r2  = __reduce_max_sync(0xFFFFFFFFu, u);
    if (__popc(bal) > 1) r2 = r1;   // duplicated max across lanes -> t2 == t1
    o1 = r1; o2 = r2;
}

// Branchless exact top-2 of 8 (FMNMX tournament)
__device__ __forceinline__ void top2_8(const float* v, float& t1, float& t2) {
    float m0 = fmaxf(v[0], v[1]), n0 = fminf(v[0], v[1]);
    float m1 = fmaxf(v[2], v[3]), n1 = fminf(v[2], v[3]);
    float m2 = fmaxf(v[4], v[5]), n2 = fminf(v[4], v[5]);
    float m3 = fmaxf(v[6], v[7]), n3 = fminf(v[6], v[7]);
    float a1 = fmaxf(m0, m1), a2 = fmaxf(fminf(m0, m1), fmaxf(n0, n1));
    float b1 = fmaxf(m2, m3), b2 = fmaxf(fminf(m2, m3), fmaxf(n2, n3));
    t1 = fmaxf(a1, b1);
    t2 = fmaxf(fminf(a1, b1), fmaxf(a2, b2));
}

// Merge (t1,t2) <- top2 of union with (q1,q2)
__device__ __forceinline__ void pair_merge(float& t1, float& t2, float q1, float q2) {
    float mn = fminf(t1, q1);
    t1 = fmaxf(t1, q1);
    t2 = fmaxf(mn, fmaxf(t2, q2));
}

__device__ __forceinline__ void top2_16(const float* v, float& t1, float& t2) {
    float p1, p2, q1, q2;
    top2_8(v, p1, p2);
    top2_8(v + 8, q1, q2);
    pair_merge(p1, p2, q1, q2);
    t1 = p1; t2 = p2;
}

__global__ __launch_bounds__(TPB)
void netsat1_kernel(const float* __restrict__ y1,
                    const float* __restrict__ y2,
                    float* __restrict__ out)
{
    __shared__ alignas(16) float sa[NSTAGE][BUF_FLOATS];
    __shared__ alignas(16) float sb[NSTAGE][BUF_FLOATS];
    __shared__ alignas(8)  unsigned long long full_b[NSTAGE];
    __shared__ alignas(8)  unsigned long long empty_b[NSTAGE];
    __shared__ float4   sw[NWARP];
    __shared__ unsigned smax[NWARP];

    const int row0 = blockIdx.x * ROWS_PER_CTA;
    const int t    = threadIdx.x;
    const int wid  = t >> 5;
    const int lid  = t & 31;

    // Pad tails so every LDS is unconditional (never touched by TMA)
    if (t < 24) {
        #pragma unroll
        for (int s = 0; s < NSTAGE; ++s) {
            sa[s][1000 + t] = -FLT_MAX;
            sb[s][1000 + t] = -FLT_MAX;
        }
    }

    uint32_t full_a[NSTAGE], empty_a[NSTAGE], sa_a[NSTAGE], sb_a[NSTAGE];
    #pragma unroll
    for (int s = 0; s < NSTAGE; ++s) {
        full_a[s]  = smem_u32(&full_b[s]);
        empty_a[s] = smem_u32(&empty_b[s]);
        sa_a[s]    = smem_u32(sa[s]);
        sb_a[s]    = smem_u32(sb[s]);
    }

    if (t == 0) {
        #pragma unroll
        for (int s = 0; s < NSTAGE; ++s) {
            asm volatile("mbarrier.init.shared.b64 [%0], %1;" :: "r"(full_a[s]),  "r"(1)   : "memory");
            asm volatile("mbarrier.init.shared.b64 [%0], %1;" :: "r"(empty_a[s]), "r"(TPB) : "memory");
        }
        asm volatile("fence.proxy.async.shared::cta;" ::: "memory");
    }
    __syncthreads();

    // Prologue: issue rows 0 and 1
    if (t == 0) {
        #pragma unroll
        for (int r = 0; r < NSTAGE; ++r) {
            const int s = r;
            asm volatile("mbarrier.arrive.expect_tx.shared.b64 _, [%0], %1;"
                         :: "r"(full_a[s]), "r"(2 * ROW_BYTES) : "memory");
            const float* src1 = y1 + (size_t)(row0 + r) * NCOLS;
            const float* src2 = y2 + (size_t)(row0 + r) * NCOLS;
            asm volatile("cp.async.bulk.shared::cluster.global.mbarrier::complete_tx::bytes [%0], [%1], %2, [%3];"
                         :: "r"(sa_a[s]), "l"(src1), "r"(ROW_BYTES), "r"(full_a[s]) : "memory");
            asm volatile("cp.async.bulk.shared::cluster.global.mbarrier::complete_tx::bytes [%0], [%1], %2, [%3];"
                         :: "r"(sb_a[s]), "l"(src2), "r"(ROW_BYTES), "r"(full_a[s]) : "memory");
        }
    }

    #pragma unroll 1
    for (int r = 0; r < ROWS_PER_CTA; ++r) {
        const int s   = r & 1;
        const int par = (r >> 1) & 1;

        // Wait for this stage's data
        MBAR_WAIT_ACQ(full_a[s], par);

        // Drain stage into registers (8 x LDS.128), then release it immediately
        const float4* av = reinterpret_cast<const float4*>(sa[s]);
        const float4* bv = reinterpret_cast<const float4*>(sb[s]);
        float a[16], b[16];
        #pragma unroll
        for (int c = 0; c < 4; ++c) {
            float4 a4 = av[t + c * TPB];
            float4 b4 = bv[t + c * TPB];
            a[4*c+0]=a4.x; a[4*c+1]=a4.y; a[4*c+2]=a4.z; a[4*c+3]=a4.w;
            b[4*c+0]=b4.x; b[4*c+1]=b4.y; b[4*c+2]=b4.z; b[4*c+3]=b4.w;
        }
        asm volatile("mbarrier.arrive.shared.b64 _, [%0];" :: "r"(empty_a[s]) : "memory");

        // Producer: refill this stage with row r+2 once all threads drained it
        if (t == 0 && r + 2 < ROWS_PER_CTA) {
            MBAR_WAIT_RLX(empty_a[s], par);
            asm volatile("mbarrier.arrive.expect_tx.shared.b64 _, [%0], %1;"
                         :: "r"(full_a[s]), "r"(2 * ROW_BYTES) : "memory");
            const float* src1 = y1 + (size_t)(row0 + r + 2) * NCOLS;
            const float* src2 = y2 + (size_t)(row0 + r + 2) * NCOLS;
            asm volatile("cp.async.bulk.shared::cluster.global.mbarrier::complete_tx::bytes [%0], [%1], %2, [%3];"
                         :: "r"(sa_a[s]), "l"(src1), "r"(ROW_BYTES), "r"(full_a[s]) : "memory");
            asm volatile("cp.async.bulk.shared::cluster.global.mbarrier::complete_tx::bytes [%0], [%1], %2, [%3];"
                         :: "r"(sb_a[s]), "l"(src2), "r"(ROW_BYTES), "r"(full_a[s]) : "memory");
        }

        // --- Pass 1: per-thread exact top-2 of 16, then warp top-2 ---
        float ta1, ta2, tb1, tb2;
        top2_16(a, ta1, ta2);
        top2_16(b, tb1, tb2);

        unsigned oa1 = ford(ta1), oa2 = ford(ta2);
        unsigned ob1 = ford(tb1), ob2 = ford(tb2);
        warp_top2(oa1, oa2);
        warp_top2(ob1, ob2);

        if (lid == 0)
            sw[wid] = make_float4(funord(oa1), funord(oa2), funord(ob1), funord(ob2));
        __syncthreads();

        float4 s0 = sw[0], s1 = sw[1];
        float t1_1 = s0.x, t2_1 = s0.y, t1_2 = s0.z, t2_2 = s0.w;
        pair_merge(t1_1, t2_1, s1.x, s1.y);
        pair_merge(t1_2, t2_2, s1.z, s1.w);

        // --- Pass 2 (registers), shifted domain ---
        const float d = t1_1 - t1_2;
        float m = -FLT_MAX;
        #pragma unroll
        for (int k = 0; k < 16; ++k)
            m = fmaxf(m, fminf(a[k], b[k] + d));

        // Cold fixup for row-argmax holders
        if ((ta1 == t1_1) || (tb1 == t1_2)) {
            #pragma unroll
            for (int k = 0; k < 16; ++k) {
                if (a[k] == t1_1 || b[k] == t1_2) {
                    float loo1 = (a[k] == t1_1) ? t2_1 : t1_1;
                    float loo2 = (b[k] == t1_2) ? t2_2 : t1_2;
                    m = fmaxf(m, fminf(a[k] - loo1, b[k] - loo2) + t1_1);  // shifted
                }
            }
        }

        // --- Block max reduce (2 warps) ---
        unsigned om = __reduce_max_sync(0xFFFFFFFFu, ford(m));
        if (lid == 0) smax[wid] = om;
        __syncthreads();
        if (t == 0)
            out[row0 + r] = funord(max(smax[0], smax[1])) - t1_1;   // un-shift
    }
}

extern "C" void kernel_launch(void* const* d_in, const int* in_sizes, int n_in,
                              void* d_out, int out_size)
{
    const float* y1 = (const float*)d_in[0];
    const float* y2 = (const float*)d_in[1];
    float* out = (float*)d_out;

    const int B = in_sizes[0] / NCOLS;           // 16384
    const int nblk = B / ROWS_PER_CTA;           // 2048
    netsat1_kernel<<<nblk, TPB>>>(y1, y2, out);
}

// round 8
// speedup vs baseline: 1.3034x; 1.3034x over previous
#include <cuda_runtime.h>
#include <cfloat>

#define NCOLS 1000
#define NVEC  250          // float4s per row per array
#define TPB   64
#define NWARP (TPB / 32)   // 2
#define TAIL_VALID (NVEC - 3 * TPB)   // 58

// Order-preserving float<->uint mapping
__device__ __forceinline__ unsigned ford(float f) {
    unsigned u = __float_as_uint(f);
    return ((int)u < 0) ? ~u : (u | 0x80000000u);
}
__device__ __forceinline__ float funord(unsigned u) {
    return __uint_as_float(((int)u < 0) ? (u ^ 0x80000000u) : ~u);
}

// Exact warp top-2 in ordered-uint domain (per-lane o1 >= o2 on entry).
__device__ __forceinline__ void warp_top2(unsigned& o1, unsigned& o2) {
    unsigned r1  = __reduce_max_sync(0xFFFFFFFFu, o1);
    unsigned bal = __ballot_sync(0xFFFFFFFFu, o1 == r1);
    unsigned u   = (o1 == r1) ? o2 : o1;
    unsigned r2  = __reduce_max_sync(0xFFFFFFFFu, u);
    if (__popc(bal) > 1) r2 = r1;   // duplicated max across lanes -> t2 == t1
    o1 = r1; o2 = r2;
}

// Branchless exact top-2 of 8 (FMNMX tournament)
__device__ __forceinline__ void top2_8(const float* v, float& t1, float& t2) {
    float m0 = fmaxf(v[0], v[1]), n0 = fminf(v[0], v[1]);
    float m1 = fmaxf(v[2], v[3]), n1 = fminf(v[2], v[3]);
    float m2 = fmaxf(v[4], v[5]), n2 = fminf(v[4], v[5]);
    float m3 = fmaxf(v[6], v[7]), n3 = fminf(v[6], v[7]);
    float a1 = fmaxf(m0, m1), a2 = fmaxf(fminf(m0, m1), fmaxf(n0, n1));
    float b1 = fmaxf(m2, m3), b2 = fmaxf(fminf(m2, m3), fmaxf(n2, n3));
    t1 = fmaxf(a1, b1);
    t2 = fmaxf(fminf(a1, b1), fmaxf(a2, b2));
}

// Merge (t1,t2) <- top2 of union with (q1,q2)
__device__ __forceinline__ void pair_merge(float& t1, float& t2, float q1, float q2) {
    float mn = fminf(t1, q1);
    t1 = fmaxf(t1, q1);
    t2 = fmaxf(mn, fmaxf(t2, q2));
}

__device__ __forceinline__ void top2_16(const float* v, float& t1, float& t2) {
    float p1, p2, q1, q2;
    top2_8(v, p1, p2);
    top2_8(v + 8, q1, q2);
    pair_merge(p1, p2, q1, q2);
    t1 = p1; t2 = p2;
}

__global__ __launch_bounds__(TPB, 12)
void netsat1_kernel(const float* __restrict__ y1,
                    const float* __restrict__ y2,
                    float* __restrict__ out)
{
    const int row = blockIdx.x;
    const int t   = threadIdx.x;
    const int wid = t >> 5;
    const int lid = t & 31;

    const float4* r1 = reinterpret_cast<const float4*>(y1 + (size_t)row * NCOLS);
    const float4* r2 = reinterpret_cast<const float4*>(y2 + (size_t)row * NCOLS);

    // All 16 loads unconditional & front-batched (tail clamped, lanes masked below)
    const bool tv   = (t < TAIL_VALID);
    const int  idx3 = tv ? (t + 3 * TPB) : t;

    float4 v0 = __ldcs(&r1[t]);
    float4 v1 = __ldcs(&r1[t + TPB]);
    float4 v2 = __ldcs(&r1[t + 2 * TPB]);
    float4 v3 = __ldcs(&r1[idx3]);
    float4 w0 = __ldcs(&r2[t]);
    float4 w1 = __ldcs(&r2[t + TPB]);
    float4 w2 = __ldcs(&r2[t + 2 * TPB]);
    float4 w3 = __ldcs(&r2[idx3]);

    float a[16], b[16];
    a[0]=v0.x; a[1]=v0.y; a[2]=v0.z; a[3]=v0.w;
    a[4]=v1.x; a[5]=v1.y; a[6]=v1.z; a[7]=v1.w;
    a[8]=v2.x; a[9]=v2.y; a[10]=v2.z; a[11]=v2.w;
    a[12] = tv ? v3.x : -FLT_MAX;  a[13] = tv ? v3.y : -FLT_MAX;
    a[14] = tv ? v3.z : -FLT_MAX;  a[15] = tv ? v3.w : -FLT_MAX;
    b[0]=w0.x; b[1]=w0.y; b[2]=w0.z; b[3]=w0.w;
    b[4]=w1.x; b[5]=w1.y; b[6]=w1.z; b[7]=w1.w;
    b[8]=w2.x; b[9]=w2.y; b[10]=w2.z; b[11]=w2.w;
    b[12] = tv ? w3.x : -FLT_MAX;  b[13] = tv ? w3.y : -FLT_MAX;
    b[14] = tv ? w3.z : -FLT_MAX;  b[15] = tv ? w3.w : -FLT_MAX;

    // --- Pass 1: per-thread exact top-2 of 16, then warp top-2 ---
    float ta1, ta2, tb1, tb2;
    top2_16(a, ta1, ta2);
    top2_16(b, tb1, tb2);

    unsigned oa1 = ford(ta1), oa2 = ford(ta2);
    unsigned ob1 = ford(tb1), ob2 = ford(tb2);
    warp_top2(oa1, oa2);
    warp_top2(ob1, ob2);

    __shared__ float4 sw[NWARP];
    __shared__ unsigned smax[NWARP];

    if (lid == 0)
        sw[wid] = make_float4(funord(oa1), funord(oa2), funord(ob1), funord(ob2));
    __syncthreads();

    // Merge the 2 warp pairs (redundant in all threads; 8 FMNMX)
    float4 s0 = sw[0], s1 = sw[1];
    float t1_1 = s0.x, t2_1 = s0.y, t1_2 = s0.z, t2_2 = s0.w;
    pair_merge(t1_1, t2_1, s1.x, s1.y);
    pair_merge(t1_2, t2_2, s1.z, s1.w);

    // --- Pass 2 (registers), shifted domain:
    // min(y1-t1_1, y2-t1_2) = min(y1, y2 + d) - t1_1,  d = t1_1 - t1_2
    const float d = t1_1 - t1_2;
    float m = -FLT_MAX;
    #pragma unroll
    for (int k = 0; k < 16; ++k)
        m = fmaxf(m, fminf(a[k], b[k] + d));

    // Fixup iff this thread holds a row-argmax element of either array (cold).
    if ((ta1 == t1_1) || (tb1 == t1_2)) {
        #pragma unroll
        for (int k = 0; k < 16; ++k) {
            if (a[k] == t1_1 || b[k] == t1_2) {
                float loo1 = (a[k] == t1_1) ? t2_1 : t1_1;
                float loo2 = (b[k] == t1_2) ? t2_2 : t1_2;
                m = fmaxf(m, fminf(a[k] - loo1, b[k] - loo2) + t1_1);  // shifted
            }
        }
    }

    // --- Block max reduce of m (2 warps) ---
    unsigned om = __reduce_max_sync(0xFFFFFFFFu, ford(m));
    if (lid == 0) smax[wid] = om;
    __syncthreads();
    if (t == 0)
        out[row] = funord(max(smax[0], smax[1])) - t1_1;   // un-shift
}

extern "C" void kernel_launch(void* const* d_in, const int* in_sizes, int n_in,
                              void* d_out, int out_size)
{
    const float* y1 = (const float*)d_in[0];
    const float* y2 = (const float*)d_in[1];
    float* out = (float*)d_out;

    const int B = in_sizes[0] / NCOLS;   // 16384
    netsat1_kernel<<<B, TPB>>>(y1, y2, out);
}